// round 16
// baseline (speedup 1.0000x reference)
#include <cuda_runtime.h>
#include <cstdint>

#define BATCH 8
#define HH 384
#define WW 384
#define PHI 32
#define RHO 64
#define NSEG 32
#define RPS (HH / NSEG)   /* 12 rows per segment, divisible by 3 */
#define NROW (RPS + 2)    /* 14: rows y0-1 .. y0+RPS */
#define GCH 8
#define NGRP (RHO / GCH)  /* 8 groups, looped INSIDE the CTA */
#define PLANE (HH * WW)

__device__ __forceinline__ uint64_t addp(uint64_t a, uint64_t b) {
    uint64_t r;
    asm("add.rn.f32x2 %0, %1, %2;" : "=l"(r) : "l"(a), "l"(b));
    return r;
}

#define LDS_V2U64(r0, r1, a) \
    asm volatile("ld.shared.v2.u64 {%0, %1}, [%2];" : "=l"(r0), "=l"(r1) : "r"(a))

#define UNPK(lo, hi, v) \
    asm("mov.b64 {%0, %1}, %2;" : "=f"(lo), "=f"(hi) : "l"(v))

__device__ __forceinline__ uint32_t smem_u32(const void* p) {
    uint32_t a;
    asm("{ .reg .u64 t; cvta.to.shared.u64 t, %1; cvt.u32.u64 %0, t; }"
        : "=r"(a) : "l"(p));
    return a;
}

// out[p, g*8+c] = relu( sum_{n in 3x3} U1[g][q_n][c] ),
// U1[g][v][c] = ((relu(v*w1+b1) @ w2 + b2) @ w3 + b3)[g*8+c] / 9, q = floor(x*255/32) in 0..7.
__global__ void __launch_bounds__(128, 6)
lpmp_deepset_kernel(const float* __restrict__ x,  const float* __restrict__ w1,
                    const float* __restrict__ b1, const float* __restrict__ w2,
                    const float* __restrict__ b2, const float* __restrict__ w3,
                    const float* __restrict__ b3, float* __restrict__ out)
{
    __shared__ __align__(16) float Tsh[8][33];     // T[q][k]
    __shared__ __align__(16) float U1[NGRP][8][8]; // [g][q][c], 2KB; row = 32B

    const int tid   = threadIdx.x;
    const int xtile = blockIdx.x;
    const int b     = blockIdx.y / NSEG;
    const int seg   = blockIdx.y % NSEG;

    // ---- prologue: build all 8 per-group LUTs ----
    #pragma unroll
    for (int e = tid; e < 8 * PHI; e += 128) {
        const int q = e >> 5, k = e & 31;
        const float fq = (float)q;
        float acc = b2[k];
        #pragma unroll
        for (int j = 0; j < PHI; j++) {
            float hv = fmaxf(fmaf(fq, w1[j], b1[j]), 0.0f);
            acc = fmaf(hv, w2[j * PHI + k], acc);
        }
        Tsh[q][k] = acc;
    }
    __syncthreads();
    #pragma unroll
    for (int i = 0; i < 4; i++) {                 // 512 entries / 128 threads
        const int e = i * 128 + tid;
        const int g = e >> 6, q = (e >> 3) & 7, c = e & 7;
        float acc = 0.0f;
        #pragma unroll
        for (int k = 0; k < PHI; k++)
            acc = fmaf(Tsh[q][k], w3[k * RHO + g * GCH + c], acc);
        U1[g][q][c] = (acc + b3[g * GCH + c]) * (1.0f / 9.0f);
    }
    __syncthreads();

    const uint32_t u1base = smem_u32(&U1[0][0][0]);

    const int x0 = xtile * 128 + tid;
    const float* __restrict__ xin = x + b * PLANE;
    const float QS = 255.0f / 32.0f;
    const int y0 = seg * RPS;

    // ---- quantize the whole segment's indices ONCE (LDG amortized over 8 groups) ----
    // pk[r]: three LUT byte-offsets (q<<5, each <= 224) packed as bytes.
    uint32_t pk[NROW];
    #pragma unroll
    for (int r = 0; r < NROW; r++) {
        const int yy = y0 - 1 + r;
        uint32_t a0 = 0, a1 = 0, a2 = 0;
        if (yy >= 0 && yy < HH) {                 // OOB row => q=0 == zero-pad semantics
            const float* row = xin + yy * WW;
            float v1 = __ldg(row + x0);
            float v0 = (x0 > 0)      ? __ldg(row + x0 - 1) : 0.0f;
            float v2 = (x0 < WW - 1) ? __ldg(row + x0 + 1) : 0.0f;
            a0 = ((uint32_t)(int)(v0 * QS)) << 5;
            a1 = ((uint32_t)(int)(v1 * QS)) << 5;
            a2 = ((uint32_t)(int)(v2 * QS)) << 5;
        }
        pk[r] = a0 | (a1 << 8) | (a2 << 16);
    }

    float* __restrict__ obase =
        out + (size_t)b * RHO * PLANE + (size_t)y0 * WW + x0;

    // Row sum for one group's table at packed index-triple p (packed f32x2).
    auto rowsumT = [&](uint32_t tb, uint32_t p, uint64_t* __restrict__ N) {
        const uint32_t a0 = tb + (p & 0xFFu);
        const uint32_t a1 = tb + ((p >> 8) & 0xFFu);
        const uint32_t a2 = tb + (p >> 16);
        uint64_t A0, A1, A2, A3, B0, B1, B2, B3, C0, C1, C2, C3;
        LDS_V2U64(A0, A1, a0);  LDS_V2U64(A2, A3, a0 + 16);
        LDS_V2U64(B0, B1, a1);  LDS_V2U64(B2, B3, a1 + 16);
        LDS_V2U64(C0, C1, a2);  LDS_V2U64(C2, C3, a2 + 16);
        N[0] = addp(addp(A0, B0), C0);
        N[1] = addp(addp(A1, B1), C1);
        N[2] = addp(addp(A2, B2), C2);
        N[3] = addp(addp(A3, B3), C3);
    };

    for (int g = 0; g < NGRP; g++) {              // dynamic: bounds I$ footprint
        const uint32_t tb = u1base + (uint32_t)g * 256u;
        float* __restrict__ og = obase + (size_t)g * GCH * PLANE;

        uint64_t R[3][4];
        rowsumT(tb, pk[0], R[0]);
        rowsumT(tb, pk[1], R[1]);

        #pragma unroll
        for (int k = 0; k < RPS; k++) {           // output rows y0..y0+11
            uint64_t* P = R[k % 3];
            uint64_t* C = R[(k + 1) % 3];
            uint64_t* N = R[(k + 2) % 3];
            rowsumT(tb, pk[k + 2], N);
            float* orow = og + k * WW;
            #pragma unroll
            for (int j = 0; j < 4; j++) {
                uint64_t s = addp(addp(P[j], C[j]), N[j]);
                float lo, hi;
                UNPK(lo, hi, s);
                orow[(2 * j + 0) * PLANE] = fmaxf(lo, 0.0f);
                orow[(2 * j + 1) * PLANE] = fmaxf(hi, 0.0f);
            }
        }
    }
}

extern "C" void kernel_launch(void* const* d_in, const int* in_sizes, int n_in,
                              void* d_out, int out_size) {
    const float* x  = (const float*)d_in[0];
    const float* w1 = (const float*)d_in[1];
    const float* b1 = (const float*)d_in[2];
    const float* w2 = (const float*)d_in[3];
    const float* b2 = (const float*)d_in[4];
    const float* w3 = (const float*)d_in[5];
    const float* b3 = (const float*)d_in[6];
    float* out = (float*)d_out;

    dim3 grid(WW / 128, BATCH * NSEG);            // 3 x 256 = 768 CTAs ~ one wave
    lpmp_deepset_kernel<<<grid, 128>>>(x, w1, b1, w2, b2, w3, b3, out);
}